// round 1
// baseline (speedup 1.0000x reference)
#include <cuda_runtime.h>

// Dims
#define BB  64
#define CC  512
#define NEE 80
#define NII 20
#define EE  512
#define DT  0.1f

// smem leading dims (bank-conflict free for the 16-lane tx access patterns)
constexpr int LDA   = 130;  // A tiles, rows=64, max K=128
constexpr int LDW   = 130;  // W tile stage A (K=128)
constexpr int LDW80 = 82;   // W tiles K=80
constexpr int LDW20 = 22;   // W tile  K=20

constexpr int AS_FLOATS = 64 * LDA;                 // 8320
constexpr int WS_FLOATS = 80 * LDW;                 // 10400
constexpr int SMEM_FLOATS = AS_FLOATS + WS_FLOATS;  // 18720
constexpr int SMEM_BYTES  = SMEM_FLOATS * 4;        // 74880

// output layout: concat(r_e_new, r_i_new, v_e_new, v_i_new)
constexpr int OFF_RI = BB * CC * NEE;            // 2,621,440
constexpr int OFF_VE = OFF_RI + BB * CC * NII;   // 3,276,800
constexpr int OFF_VI = OFF_VE + BB * CC * NEE;   // 5,898,240

template <int KLEN, int LDWX>
__device__ __forceinline__ void gemm_e(const float* __restrict__ arow,
                                       const float* __restrict__ wrow,
                                       float accE[4][5]) {
#pragma unroll 4
    for (int k = 0; k < KLEN; k += 2) {
        float2 a[4], w[5];
#pragma unroll
        for (int i = 0; i < 4; i++) a[i] = *(const float2*)(arow + i * LDA + k);
#pragma unroll
        for (int j = 0; j < 5; j++) w[j] = *(const float2*)(wrow + j * LDWX + k);
#pragma unroll
        for (int i = 0; i < 4; i++) {
#pragma unroll
            for (int j = 0; j < 5; j++) {
                accE[i][j] = fmaf(a[i].x, w[j].x, accE[i][j]);
                accE[i][j] = fmaf(a[i].y, w[j].y, accE[i][j]);
            }
        }
    }
}

__global__ void __launch_bounds__(256, 3)
ei_kernel(const float* __restrict__ thal,
          const float* __restrict__ thal_inc,
          const float* __restrict__ l23_fb,
          const float* __restrict__ r_e,
          const float* __restrict__ r_i,
          const float* __restrict__ e_v,
          const float* __restrict__ i_v,
          const float* __restrict__ input_proj,
          const float* __restrict__ feedback_proj,
          const float* __restrict__ W_ee,
          const float* __restrict__ W_ei,
          const float* __restrict__ W_ie,
          float* __restrict__ out) {
    extern __shared__ float smem[];
    float* As = smem;
    float* Ws = smem + AS_FLOATS;

    const int c  = blockIdx.x;
    const int t  = threadIdx.x;
    const int tx = t & 15;   // 16 lanes -> o tiles of 5
    const int ty = t >> 4;   // 16 -> b tiles of 4

    float accE[4][5];
    float accI[5];
#pragma unroll
    for (int i = 0; i < 4; i++)
#pragma unroll
        for (int j = 0; j < 5; j++) accE[i][j] = 0.f;
#pragma unroll
    for (int j = 0; j < 5; j++) accI[j] = 0.f;

    const float* arowE = As + (ty * 4) * LDA;

    // ================= Stage A: I_ext, K = 512 in 4 chunks of 128 ============
    for (int kk = 0; kk < EE; kk += 128) {
        // thal_full chunk [64][128]
        for (int idx = t; idx < 64 * 32; idx += 256) {
            int b = idx >> 5, e4 = (idx & 31) << 2;
            float4 th = *(const float4*)(thal + b * EE + kk + e4);
            float4 ti = *(const float4*)(thal_inc + (b * CC + c) * EE + kk + e4);
            float* dst = As + b * LDA + e4;
            dst[0] = th.x + ti.x; dst[1] = th.y + ti.y;
            dst[2] = th.z + ti.z; dst[3] = th.w + ti.w;
        }
        // input_proj chunk [80][128]
        for (int idx = t; idx < 80 * 32; idx += 256) {
            int o = idx >> 5, e4 = (idx & 31) << 2;
            float4 w = *(const float4*)(input_proj + (c * NEE + o) * EE + kk + e4);
            float* dst = Ws + o * LDW + e4;
            dst[0] = w.x; dst[1] = w.y; dst[2] = w.z; dst[3] = w.w;
        }
        __syncthreads();
        gemm_e<128, LDW>(arowE, Ws + (tx * 5) * LDW, accE);
        __syncthreads();
    }

    // ================= Stage B: I_fb, K = 80 =================================
    for (int idx = t; idx < 64 * 20; idx += 256) {
        int b = idx / 20, e4 = (idx % 20) << 2;
        float4 v = *(const float4*)(l23_fb + (b * CC + c) * NEE + e4);
        float* dst = As + b * LDA + e4;
        dst[0] = v.x; dst[1] = v.y; dst[2] = v.z; dst[3] = v.w;
    }
    for (int idx = t; idx < 80 * 20; idx += 256) {
        int o = idx / 20, e4 = (idx % 20) << 2;
        float4 v = *(const float4*)(feedback_proj + (c * NEE + o) * NEE + e4);
        float* dst = Ws + o * LDW80 + e4;
        dst[0] = v.x; dst[1] = v.y; dst[2] = v.z; dst[3] = v.w;
    }
    __syncthreads();
    gemm_e<80, LDW80>(arowE, Ws + (tx * 5) * LDW80, accE);
    __syncthreads();

    // ================= Stage C: I_ee (into accE) + I_ei (into accI), K = 80 ==
    float* Wei = Ws + 80 * LDW80;  // 6560..8200 inside Ws region
    for (int idx = t; idx < 64 * 20; idx += 256) {
        int b = idx / 20, e4 = (idx % 20) << 2;
        float4 v = *(const float4*)(r_e + (b * CC + c) * NEE + e4);
        float* dst = As + b * LDA + e4;
        dst[0] = v.x; dst[1] = v.y; dst[2] = v.z; dst[3] = v.w;
    }
    for (int idx = t; idx < 80 * 20; idx += 256) {
        int o = idx / 20, e4 = (idx % 20) << 2;
        float4 v = *(const float4*)(W_ee + (c * NEE + o) * NEE + e4);
        float* dst = Ws + o * LDW80 + e4;
        dst[0] = v.x; dst[1] = v.y; dst[2] = v.z; dst[3] = v.w;
    }
    for (int idx = t; idx < 20 * 20; idx += 256) {
        int o = idx / 20, e4 = (idx % 20) << 2;
        float4 v = *(const float4*)(W_ei + (c * NII + o) * NEE + e4);
        float* dst = Wei + o * LDW80 + e4;
        dst[0] = v.x; dst[1] = v.y; dst[2] = v.z; dst[3] = v.w;
    }
    __syncthreads();
    gemm_e<80, LDW80>(arowE, Ws + (tx * 5) * LDW80, accE);
    {
        const int   bi    = ty * 4 + (tx >> 2);
        const float* airow = As + bi * LDA;
        const float* wirow = Wei + ((tx & 3) * 5) * LDW80;
#pragma unroll 4
        for (int k = 0; k < 80; k += 2) {
            float2 ai = *(const float2*)(airow + k);
            float2 wi[5];
#pragma unroll
            for (int j = 0; j < 5; j++) wi[j] = *(const float2*)(wirow + j * LDW80 + k);
#pragma unroll
            for (int j = 0; j < 5; j++) {
                accI[j] = fmaf(ai.x, wi[j].x, accI[j]);
                accI[j] = fmaf(ai.y, wi[j].y, accI[j]);
            }
        }
    }
    __syncthreads();

    // ================= Stage D: I_ie (negated into accE), K = 20 =============
    for (int idx = t; idx < 64 * 5; idx += 256) {
        int b = idx / 5, e4 = (idx % 5) << 2;
        float4 v = *(const float4*)(r_i + (b * CC + c) * NII + e4);
        float* dst = As + b * LDA + e4;
        dst[0] = v.x; dst[1] = v.y; dst[2] = v.z; dst[3] = v.w;
    }
    for (int idx = t; idx < 80 * 5; idx += 256) {
        int o = idx / 5, e4 = (idx % 5) << 2;
        float4 v = *(const float4*)(W_ie + (c * NEE + o) * NII + e4);
        float* dst = Ws + o * LDW20 + e4;
        // store negated so the shared gemm accumulates -r_i * W_ie
        dst[0] = -v.x; dst[1] = -v.y; dst[2] = -v.z; dst[3] = -v.w;
    }
    __syncthreads();
    gemm_e<20, LDW20>(arowE, Ws + (tx * 5) * LDW20, accE);

    // ================= Epilogue: leaky integration + relu ====================
#pragma unroll
    for (int i = 0; i < 4; i++) {
        int b = ty * 4 + i;
#pragma unroll
        for (int j = 0; j < 5; j++) {
            int o   = tx * 5 + j;
            int idx = (b * CC + c) * NEE + o;
            float ev = e_v[idx];
            float v  = ev + DT * (accE[i][j] - ev);
            out[idx]          = fmaxf(v, 0.f);
            out[OFF_VE + idx] = v;
        }
    }
    {
        int bi = ty * 4 + (tx >> 2);
#pragma unroll
        for (int j = 0; j < 5; j++) {
            int oi  = (tx & 3) * 5 + j;
            int idx = (bi * CC + c) * NII + oi;
            float iv = i_v[idx];
            float v  = iv + DT * (accI[j] - iv);
            out[OFF_RI + idx] = fmaxf(v, 0.f);
            out[OFF_VI + idx] = v;
        }
    }
}

extern "C" void kernel_launch(void* const* d_in, const int* in_sizes, int n_in,
                              void* d_out, int out_size) {
    (void)in_sizes; (void)n_in; (void)out_size;
    cudaFuncSetAttribute(ei_kernel, cudaFuncAttributeMaxDynamicSharedMemorySize,
                         SMEM_BYTES);
    ei_kernel<<<CC, 256, SMEM_BYTES>>>(
        (const float*)d_in[0],   // thal
        (const float*)d_in[1],   // thal_increments
        (const float*)d_in[2],   // l23_fb
        (const float*)d_in[3],   // r_e
        (const float*)d_in[4],   // r_i
        (const float*)d_in[5],   // e_v
        (const float*)d_in[6],   // i_v
        (const float*)d_in[7],   // input_proj
        (const float*)d_in[8],   // feedback_proj
        (const float*)d_in[9],   // W_ee
        (const float*)d_in[10],  // W_ei
        (const float*)d_in[11],  // W_ie
        (float*)d_out);
}

// round 3
// speedup vs baseline: 1.5997x; 1.5997x over previous
#include <cuda_runtime.h>
#include <cstdint>

constexpr int B_ = 64, C_ = 512, NE_ = 80, NI_ = 20, E_ = 512;
#define DTC 0.1f

// smem geometry (floats). LDS row stride 68 -> (4*row + col) % 32 distinct for
// the m16n8k8 fragment pattern (rows lane/4 = 0..7, cols lane%4 (+4)).
constexpr int LDS_ = 68;
constexpr int A_FLOATS = 64 * LDS_;    // 4352
constexpr int W_FLOATS = 104 * LDS_;   // 7072 (80 W rows + 24 for W_ei/pad)
constexpr int SMEM_FLOATS = 2 * A_FLOATS + 2 * W_FLOATS;   // 22848
constexpr int SMEM_BYTES  = SMEM_FLOATS * 4;               // 91392 -> 2 CTAs/SM

// output layout: concat(r_e_new, r_i_new, v_e_new, v_i_new)
constexpr size_t OFF_RI = (size_t)B_ * C_ * NE_;
constexpr size_t OFF_VE = OFF_RI + (size_t)B_ * C_ * NI_;
constexpr size_t OFF_VI = OFF_VE + (size_t)B_ * C_ * NE_;

// ---------------- helpers ----------------
__device__ __forceinline__ uint32_t s2u(const void* p) {
    uint32_t a;
    asm("{ .reg .u64 t; cvta.to.shared.u64 t, %1; cvt.u32.u64 %0, t; }" : "=r"(a) : "l"(p));
    return a;
}
__device__ __forceinline__ void cpa16(uint32_t dst, const float* src) {
    asm volatile("cp.async.cg.shared.global [%0], [%1], 16;" :: "r"(dst), "l"(src));
}
__device__ __forceinline__ void cpa16z(uint32_t dst, const float* src) {
    asm volatile("cp.async.cg.shared.global [%0], [%1], 16, 0;" :: "r"(dst), "l"(src));
}
#define CP_COMMIT() asm volatile("cp.async.commit_group;" ::: "memory")
#define CP_WAIT1()  asm volatile("cp.async.wait_group 1;" ::: "memory")
#define CP_WAIT0()  asm volatile("cp.async.wait_group 0;" ::: "memory")

__device__ __forceinline__ uint32_t tf32(float x) {
    uint32_t r;
    asm("cvt.rna.tf32.f32 %0, %1;" : "=r"(r) : "f"(x));
    return r;
}
__device__ __forceinline__ void mma8(float d[4], uint32_t a0, uint32_t a1,
                                     uint32_t a2, uint32_t a3,
                                     uint32_t b0, uint32_t b1) {
    asm("mma.sync.aligned.m16n8k8.row.col.f32.tf32.tf32.f32 "
        "{%0,%1,%2,%3}, {%4,%5,%6,%7}, {%8,%9}, {%0,%1,%2,%3};"
        : "+f"(d[0]), "+f"(d[1]), "+f"(d[2]), "+f"(d[3])
        : "r"(a0), "r"(a1), "r"(a2), "r"(a3), "r"(b0), "r"(b1));
}

// ---------------- chunk prefetch (cp.async) ----------------
// chunks: 0-7  I_ext   (A=thal_inc, W=input_proj, k0=ci*64, kl=64)
//         8,9  I_fb    (A=l23_fb,   W=feedback_proj, kl=64,16)
//         10,11 I_ee+I_ei (A=r_e, W=W_ee rows 0-79 + W_ei rows 80-99, kl=64,16)
//         12   I_ie    (A=r_i zero-padded 20->24, W=W_ie, kl=24)
__device__ __forceinline__ void prefetch(
    int ci, int buf, int c, int t, float* sm,
    const float* thal_inc, const float* l23_fb, const float* r_e,
    const float* r_i, const float* input_proj, const float* feedback_proj,
    const float* W_ee, const float* W_ei, const float* W_ie) {
    const uint32_t asb = s2u(sm + buf * A_FLOATS);
    const uint32_t wsb = s2u(sm + 2 * A_FLOATS + buf * W_FLOATS);

    if (ci < 8) {
        const int k0 = ci * 64;
        for (int idx = t; idx < 1024 + 1280; idx += 256) {
            if (idx < 1024) {
                int row = idx >> 4, g = idx & 15;
                cpa16(asb + (row * LDS_ + g * 4) * 4,
                      thal_inc + ((size_t)row * C_ + c) * E_ + k0 + g * 4);
            } else {
                int j = idx - 1024, row = j >> 4, g = j & 15;
                cpa16(wsb + (row * LDS_ + g * 4) * 4,
                      input_proj + ((size_t)c * NE_ + row) * E_ + k0 + g * 4);
            }
        }
    } else if (ci == 8 || ci == 10) {
        const float* Ap = (ci == 8) ? l23_fb : r_e;
        const float* Wp = (ci == 8) ? feedback_proj : W_ee;
        const int tot = (ci == 10) ? 1024 + 1280 + 320 : 1024 + 1280;
        for (int idx = t; idx < tot; idx += 256) {
            if (idx < 1024) {
                int row = idx >> 4, g = idx & 15;
                cpa16(asb + (row * LDS_ + g * 4) * 4,
                      Ap + ((size_t)row * C_ + c) * NE_ + g * 4);
            } else if (idx < 1024 + 1280) {
                int j = idx - 1024, row = j >> 4, g = j & 15;
                cpa16(wsb + (row * LDS_ + g * 4) * 4,
                      Wp + ((size_t)c * NE_ + row) * NE_ + g * 4);
            } else {
                int j = idx - (1024 + 1280), row = j >> 4, g = j & 15;
                cpa16(wsb + ((80 + row) * LDS_ + g * 4) * 4,
                      W_ei + ((size_t)c * NI_ + row) * NE_ + g * 4);
            }
        }
    } else if (ci == 9 || ci == 11) {
        const float* Ap = (ci == 9) ? l23_fb : r_e;
        const float* Wp = (ci == 9) ? feedback_proj : W_ee;
        const int tot = (ci == 11) ? 256 + 320 + 80 : 256 + 320;
        for (int idx = t; idx < tot; idx += 256) {
            if (idx < 256) {
                int row = idx >> 2, g = idx & 3;
                cpa16(asb + (row * LDS_ + g * 4) * 4,
                      Ap + ((size_t)row * C_ + c) * NE_ + 64 + g * 4);
            } else if (idx < 256 + 320) {
                int j = idx - 256, row = j >> 2, g = j & 3;
                cpa16(wsb + (row * LDS_ + g * 4) * 4,
                      Wp + ((size_t)c * NE_ + row) * NE_ + 64 + g * 4);
            } else {
                int j = idx - (256 + 320), row = j >> 2, g = j & 3;
                cpa16(wsb + ((80 + row) * LDS_ + g * 4) * 4,
                      W_ei + ((size_t)c * NI_ + row) * NE_ + 64 + g * 4);
            }
        }
    } else {  // ci == 12
        for (int idx = t; idx < 384 + 400; idx += 256) {
            if (idx < 384) {
                int row = idx / 6, g = idx % 6;
                const float* src = r_i + ((size_t)row * C_ + c) * NI_ + ((g < 5) ? g * 4 : 0);
                uint32_t dst = asb + (row * LDS_ + g * 4) * 4;
                if (g < 5) cpa16(dst, src);
                else       cpa16z(dst, src);   // zero-fill cols 20..23
            } else {
                int j = idx - 384, row = j / 5, g = j % 5;
                cpa16(wsb + (row * LDS_ + g * 4) * 4,
                      W_ie + ((size_t)c * NE_ + row) * NI_ + g * 4);
            }
        }
    }
}

// ---------------- per-chunk mma ----------------
__device__ __forceinline__ void compute_chunk(
    const float* __restrict__ As, const float* __restrict__ Ws, int ksteps,
    const float* __restrict__ thalp, int k0c, bool doI, bool neg,
    int m0, int wn, int lm, int lc, float accE[5][4], float accI[3][4]) {
#pragma unroll 2
    for (int k = 0; k < ksteps; k++) {
        const int kb = k * 8;
        const float* ar0 = As + (m0 + lm) * LDS_ + kb + lc;
        const float* ar1 = ar0 + 8 * LDS_;
        float f0 = ar0[0], f2 = ar0[4];
        float f1 = ar1[0], f3 = ar1[4];
        if (thalp) {
            const float* tp0 = thalp + (m0 + lm) * E_ + k0c + kb + lc;
            const float* tp1 = tp0 + 8 * E_;
            f0 += __ldg(tp0); f2 += __ldg(tp0 + 4);
            f1 += __ldg(tp1); f3 += __ldg(tp1 + 4);
        }
        if (neg) { f0 = -f0; f1 = -f1; f2 = -f2; f3 = -f3; }
        const uint32_t a0 = tf32(f0), a1 = tf32(f1), a2 = tf32(f2), a3 = tf32(f3);
#pragma unroll
        for (int j = 0; j < 5; j++) {
            const float* wr = Ws + (wn * 40 + j * 8 + lm) * LDS_ + kb + lc;
            mma8(accE[j], a0, a1, a2, a3, tf32(wr[0]), tf32(wr[4]));
        }
        if (doI && wn == 0) {
#pragma unroll
            for (int j = 0; j < 3; j++) {
                const float* wr = Ws + (80 + j * 8 + lm) * LDS_ + kb + lc;
                mma8(accI[j], a0, a1, a2, a3, tf32(wr[0]), tf32(wr[4]));
            }
        }
    }
}

__global__ void __launch_bounds__(256, 2)
ei_mma(const float* __restrict__ thal, const float* __restrict__ thal_inc,
       const float* __restrict__ l23_fb, const float* __restrict__ r_e,
       const float* __restrict__ r_i, const float* __restrict__ e_v,
       const float* __restrict__ i_v, const float* __restrict__ input_proj,
       const float* __restrict__ feedback_proj, const float* __restrict__ W_ee,
       const float* __restrict__ W_ei, const float* __restrict__ W_ie,
       float* __restrict__ out) {
    extern __shared__ float sm[];
    const int t = threadIdx.x, c = blockIdx.x;
    const int w = t >> 5, lane = t & 31;
    const int wm = w >> 1, wn = w & 1;
    const int m0 = wm * 16, lm = lane >> 2, lc = lane & 3;

    float accE[5][4], accI[3][4];
#pragma unroll
    for (int j = 0; j < 5; j++)
#pragma unroll
        for (int q = 0; q < 4; q++) accE[j][q] = 0.f;
#pragma unroll
    for (int j = 0; j < 3; j++)
#pragma unroll
        for (int q = 0; q < 4; q++) accI[j][q] = 0.f;

    prefetch(0, 0, c, t, sm, thal_inc, l23_fb, r_e, r_i,
             input_proj, feedback_proj, W_ee, W_ei, W_ie);
    CP_COMMIT();

    for (int ci = 0; ci < 13; ci++) {
        if (ci < 12) {
            prefetch(ci + 1, (ci + 1) & 1, c, t, sm, thal_inc, l23_fb, r_e, r_i,
                     input_proj, feedback_proj, W_ee, W_ei, W_ie);
            CP_COMMIT();
            CP_WAIT1();
        } else {
            CP_WAIT0();
        }
        __syncthreads();
        const float* As = sm + (ci & 1) * A_FLOATS;
        const float* Ws = sm + 2 * A_FLOATS + (ci & 1) * W_FLOATS;
        const int ks = (ci <= 8) ? 8 : (ci == 10) ? 8 : (ci == 12) ? 3 : 2;
        compute_chunk(As, Ws, ks,
                      (ci < 8) ? thal : nullptr, ci * 64,
                      (ci == 10 || ci == 11), (ci == 12),
                      m0, wn, lm, lc, accE, accI);
        __syncthreads();
    }

    // ---------------- epilogue: leaky integration + relu ----------------
    const int r0 = m0 + lm, r1 = r0 + 8;
#pragma unroll
    for (int j = 0; j < 5; j++) {
        const int col = wn * 40 + j * 8 + 2 * lc;
        const size_t i0 = ((size_t)r0 * C_ + c) * NE_ + col;
        const size_t i1 = ((size_t)r1 * C_ + c) * NE_ + col;
        float2 ev0 = *(const float2*)(e_v + i0);
        float2 ev1 = *(const float2*)(e_v + i1);
        float v0x = ev0.x + DTC * (accE[j][0] - ev0.x);
        float v0y = ev0.y + DTC * (accE[j][1] - ev0.y);
        float v1x = ev1.x + DTC * (accE[j][2] - ev1.x);
        float v1y = ev1.y + DTC * (accE[j][3] - ev1.y);
        *(float2*)(out + i0)          = make_float2(fmaxf(v0x, 0.f), fmaxf(v0y, 0.f));
        *(float2*)(out + i1)          = make_float2(fmaxf(v1x, 0.f), fmaxf(v1y, 0.f));
        *(float2*)(out + OFF_VE + i0) = make_float2(v0x, v0y);
        *(float2*)(out + OFF_VE + i1) = make_float2(v1x, v1y);
    }
    if (wn == 0) {
#pragma unroll
        for (int j = 0; j < 3; j++) {
            const int col = j * 8 + 2 * lc;
            if (col < NI_) {
                const size_t i0 = ((size_t)r0 * C_ + c) * NI_ + col;
                const size_t i1 = ((size_t)r1 * C_ + c) * NI_ + col;
                float2 iv0 = *(const float2*)(i_v + i0);
                float2 iv1 = *(const float2*)(i_v + i1);
                float v0x = iv0.x + DTC * (accI[j][0] - iv0.x);
                float v0y = iv0.y + DTC * (accI[j][1] - iv0.y);
                float v1x = iv1.x + DTC * (accI[j][2] - iv1.x);
                float v1y = iv1.y + DTC * (accI[j][3] - iv1.y);
                *(float2*)(out + OFF_RI + i0) = make_float2(fmaxf(v0x, 0.f), fmaxf(v0y, 0.f));
                *(float2*)(out + OFF_RI + i1) = make_float2(fmaxf(v1x, 0.f), fmaxf(v1y, 0.f));
                *(float2*)(out + OFF_VI + i0) = make_float2(v0x, v0y);
                *(float2*)(out + OFF_VI + i1) = make_float2(v1x, v1y);
            }
        }
    }
}

extern "C" void kernel_launch(void* const* d_in, const int* in_sizes, int n_in,
                              void* d_out, int out_size) {
    (void)in_sizes; (void)n_in; (void)out_size;
    cudaFuncSetAttribute(ei_mma, cudaFuncAttributeMaxDynamicSharedMemorySize,
                         SMEM_BYTES);
    ei_mma<<<C_, 256, SMEM_BYTES>>>(
        (const float*)d_in[0],   // thal
        (const float*)d_in[1],   // thal_increments
        (const float*)d_in[2],   // l23_fb
        (const float*)d_in[3],   // r_e
        (const float*)d_in[4],   // r_i
        (const float*)d_in[5],   // e_v
        (const float*)d_in[6],   // i_v
        (const float*)d_in[7],   // input_proj
        (const float*)d_in[8],   // feedback_proj
        (const float*)d_in[9],   // W_ee
        (const float*)d_in[10],  // W_ei
        (const float*)d_in[11],  // W_ie
        (float*)d_out);
}

// round 4
// speedup vs baseline: 1.7639x; 1.1026x over previous
#include <cuda_runtime.h>
#include <cstdint>

constexpr int B_ = 64, C_ = 512, NE_ = 80, NI_ = 20, E_ = 512;
#define DTC 0.1f

// K-chunk = 32. smem rows stride 40 floats (160B): row*40 mod 32 = row*8 ->
// conflict-free for the float2 fragment pattern and the cp.async stores.
constexpr int LDSW = 40;
constexpr int A_F  = 64 * LDSW;            // 2560 floats
constexpr int W_F  = 104 * LDSW;           // 4160 floats (80 W + 24 W_ei/pad)
constexpr int PAIR_F = A_F + W_F;          // 6720
constexpr int SMEM_BYTES = 2 * PAIR_F * 4; // 53760 -> 3 CTAs/SM

constexpr size_t OFF_RI = (size_t)B_ * C_ * NE_;
constexpr size_t OFF_VE = OFF_RI + (size_t)B_ * C_ * NI_;
constexpr size_t OFF_VI = OFF_VE + (size_t)B_ * C_ * NE_;

// ---------------- helpers ----------------
__device__ __forceinline__ uint32_t s2u(const void* p) {
    uint32_t a;
    asm("{ .reg .u64 t; cvta.to.shared.u64 t, %1; cvt.u32.u64 %0, t; }" : "=r"(a) : "l"(p));
    return a;
}
__device__ __forceinline__ void cpa16(uint32_t dst, const float* src) {
    asm volatile("cp.async.cg.shared.global [%0], [%1], 16;" :: "r"(dst), "l"(src));
}
__device__ __forceinline__ void cpa16z(uint32_t dst, const float* src) {
    asm volatile("cp.async.cg.shared.global [%0], [%1], 16, 0;" :: "r"(dst), "l"(src));
}
#define CP_COMMIT() asm volatile("cp.async.commit_group;" ::: "memory")
#define CP_WAIT1()  asm volatile("cp.async.wait_group 1;" ::: "memory")
#define CP_WAIT0()  asm volatile("cp.async.wait_group 0;" ::: "memory")

// pack two f32 -> bf16x2 (lo = x, hi = y)
__device__ __forceinline__ uint32_t bfx2(float2 f) {
    uint32_t r;
    asm("cvt.rn.bf16x2.f32 %0, %1, %2;" : "=r"(r) : "f"(f.y), "f"(f.x));
    return r;
}
__device__ __forceinline__ void mma16(float d[4], uint32_t a0, uint32_t a1,
                                      uint32_t a2, uint32_t a3,
                                      uint32_t b0, uint32_t b1) {
    asm("mma.sync.aligned.m16n8k16.row.col.f32.bf16.bf16.f32 "
        "{%0,%1,%2,%3}, {%4,%5,%6,%7}, {%8,%9}, {%0,%1,%2,%3};"
        : "+f"(d[0]), "+f"(d[1]), "+f"(d[2]), "+f"(d[3])
        : "r"(a0), "r"(a1), "r"(a2), "r"(a3), "r"(b0), "r"(b1));
}

// ---------------- chunk prefetch ----------------
// chunks: 0-15  I_ext   (A=thal_inc, W=input_proj), k0=ci*32
//         16-18 I_fb    (A=l23_fb, W=feedback_proj), K=80 padded 96
//         19-21 I_ee/ei (A=r_e, W=W_ee + W_ei rows 80-99), K=80 padded 96
//         22    I_ie    (A=r_i, W=W_ie), K=20 padded 32
__device__ __forceinline__ void prefetch(
    int ci, int buf, int c, int t, float* sm,
    const float* thal_inc, const float* l23_fb, const float* r_e,
    const float* r_i, const float* input_proj, const float* feedback_proj,
    const float* W_ee, const float* W_ei, const float* W_ie) {
    const uint32_t asb = s2u(sm + buf * PAIR_F);
    const uint32_t wsb = asb + A_F * 4;

    if (ci < 16) {
        const int k0 = ci * 32;
        for (int idx = t; idx < 1152; idx += 256) {
            if (idx < 512) {
                int row = idx >> 3, g = idx & 7;
                cpa16(asb + (row * LDSW + g * 4) * 4,
                      thal_inc + ((size_t)row * C_ + c) * E_ + k0 + g * 4);
            } else {
                int j = idx - 512, row = j >> 3, g = j & 7;
                cpa16(wsb + (row * LDSW + g * 4) * 4,
                      input_proj + ((size_t)c * NE_ + row) * E_ + k0 + g * 4);
            }
        }
    } else if (ci < 22) {
        const bool isB = ci < 19;
        const int k0 = (ci - (isB ? 16 : 19)) * 32;
        const float* Ap = isB ? l23_fb : r_e;
        const float* Wp = isB ? feedback_proj : W_ee;
        const int tot = isB ? 1152 : 1312;
        for (int idx = t; idx < tot; idx += 256) {
            if (idx < 512) {
                int row = idx >> 3, g = idx & 7, col = k0 + g * 4;
                uint32_t dst = asb + (row * LDSW + g * 4) * 4;
                const float* src = Ap + ((size_t)row * C_ + c) * NE_;
                if (col < NE_) cpa16(dst, src + col); else cpa16z(dst, src);
            } else if (idx < 1152) {
                int j = idx - 512, row = j >> 3, g = j & 7, col = k0 + g * 4;
                uint32_t dst = wsb + (row * LDSW + g * 4) * 4;
                const float* src = Wp + ((size_t)c * NE_ + row) * NE_;
                if (col < NE_) cpa16(dst, src + col); else cpa16z(dst, src);
            } else {
                int j = idx - 1152, row = j >> 3, g = j & 7, col = k0 + g * 4;
                uint32_t dst = wsb + ((80 + row) * LDSW + g * 4) * 4;
                const float* src = W_ei + ((size_t)c * NI_ + row) * NE_;
                if (col < NE_) cpa16(dst, src + col); else cpa16z(dst, src);
            }
        }
    } else {
        for (int idx = t; idx < 1152; idx += 256) {
            if (idx < 512) {
                int row = idx >> 3, g = idx & 7;
                uint32_t dst = asb + (row * LDSW + g * 4) * 4;
                const float* src = r_i + ((size_t)row * C_ + c) * NI_;
                if (g < 5) cpa16(dst, src + g * 4); else cpa16z(dst, src);
            } else {
                int j = idx - 512, row = j >> 3, g = j & 7;
                uint32_t dst = wsb + (row * LDSW + g * 4) * 4;
                const float* src = W_ie + ((size_t)c * NE_ + row) * NI_;
                if (g < 5) cpa16(dst, src + g * 4); else cpa16z(dst, src);
            }
        }
    }
}

// ---------------- per-chunk compute: 2 x k16 bf16 mma ----------------
__device__ __forceinline__ void compute2(
    const float* __restrict__ As, const float* __restrict__ Ws,
    bool doI, bool neg, int m0, int wn, int lm, int lc,
    float accE[5][4], float accI[3][4]) {
#pragma unroll
    for (int kb = 0; kb < 32; kb += 16) {
        const float* ap = As + (m0 + lm) * LDSW + kb + 2 * lc;
        float2 fa0 = *(const float2*)(ap);
        float2 fa1 = *(const float2*)(ap + 8 * LDSW);
        float2 fa2 = *(const float2*)(ap + 8);
        float2 fa3 = *(const float2*)(ap + 8 * LDSW + 8);
        if (neg) {
            fa0.x = -fa0.x; fa0.y = -fa0.y; fa1.x = -fa1.x; fa1.y = -fa1.y;
            fa2.x = -fa2.x; fa2.y = -fa2.y; fa3.x = -fa3.x; fa3.y = -fa3.y;
        }
        const uint32_t a0 = bfx2(fa0), a1 = bfx2(fa1), a2 = bfx2(fa2), a3 = bfx2(fa3);
#pragma unroll
        for (int j = 0; j < 5; j++) {
            const float* wp = Ws + (wn * 40 + j * 8 + lm) * LDSW + kb + 2 * lc;
            uint32_t b0 = bfx2(*(const float2*)(wp));
            uint32_t b1 = bfx2(*(const float2*)(wp + 8));
            mma16(accE[j], a0, a1, a2, a3, b0, b1);
        }
        if (doI && wn == 0) {
#pragma unroll
            for (int j = 0; j < 3; j++) {
                const float* wp = Ws + (80 + j * 8 + lm) * LDSW + kb + 2 * lc;
                uint32_t b0 = bfx2(*(const float2*)(wp));
                uint32_t b1 = bfx2(*(const float2*)(wp + 8));
                mma16(accI[j], a0, a1, a2, a3, b0, b1);
            }
        }
    }
}

__global__ void __launch_bounds__(256, 3)
ei_bf16(const float* __restrict__ thal, const float* __restrict__ thal_inc,
        const float* __restrict__ l23_fb, const float* __restrict__ r_e,
        const float* __restrict__ r_i, const float* __restrict__ e_v,
        const float* __restrict__ i_v, const float* __restrict__ input_proj,
        const float* __restrict__ feedback_proj, const float* __restrict__ W_ee,
        const float* __restrict__ W_ei, const float* __restrict__ W_ie,
        float* __restrict__ out) {
    extern __shared__ float sm[];
    const int t = threadIdx.x, c = blockIdx.x;
    const int w = t >> 5, lane = t & 31;
    const int wm = w >> 1, wn = w & 1;
    const int m0 = wm * 16, lm = lane >> 2, lc = lane & 3;

    float accE[5][4], accI[3][4];
#pragma unroll
    for (int j = 0; j < 5; j++)
#pragma unroll
        for (int q = 0; q < 4; q++) accE[j][q] = 0.f;
#pragma unroll
    for (int j = 0; j < 3; j++)
#pragma unroll
        for (int q = 0; q < 4; q++) accI[j][q] = 0.f;

    prefetch(0, 0, c, t, sm, thal_inc, l23_fb, r_e, r_i,
             input_proj, feedback_proj, W_ee, W_ei, W_ie);
    CP_COMMIT();

    for (int ci = 0; ci < 23; ci++) {
        if (ci < 22) {
            prefetch(ci + 1, (ci + 1) & 1, c, t, sm, thal_inc, l23_fb, r_e, r_i,
                     input_proj, feedback_proj, W_ee, W_ei, W_ie);
            CP_COMMIT();
            CP_WAIT1();
        } else {
            CP_WAIT0();
        }
        __syncthreads();
        float* As = sm + (ci & 1) * PAIR_F;
        const float* Ws = As + A_F;
        if (ci < 16) {
            // fixup: add broadcast thal slice into the A tile (L2-hot LDG)
            const int k0 = ci * 32;
            for (int idx = t; idx < 512; idx += 256) {
                int row = idx >> 3, g = idx & 7;
                float4 a = *(const float4*)(As + row * LDSW + g * 4);
                float4 th = __ldg((const float4*)(thal + (size_t)row * E_ + k0 + g * 4));
                a.x += th.x; a.y += th.y; a.z += th.z; a.w += th.w;
                *(float4*)(As + row * LDSW + g * 4) = a;
            }
            __syncthreads();
        }
        compute2(As, Ws, (ci >= 19 && ci < 22), ci == 22,
                 m0, wn, lm, lc, accE, accI);
        __syncthreads();
    }

    // ---------------- epilogue: leaky integration + relu ----------------
    const int r0 = m0 + lm, r1 = r0 + 8;
#pragma unroll
    for (int j = 0; j < 5; j++) {
        const int col = wn * 40 + j * 8 + 2 * lc;
        const size_t i0 = ((size_t)r0 * C_ + c) * NE_ + col;
        const size_t i1 = ((size_t)r1 * C_ + c) * NE_ + col;
        float2 ev0 = *(const float2*)(e_v + i0);
        float2 ev1 = *(const float2*)(e_v + i1);
        float v0x = ev0.x + DTC * (accE[j][0] - ev0.x);
        float v0y = ev0.y + DTC * (accE[j][1] - ev0.y);
        float v1x = ev1.x + DTC * (accE[j][2] - ev1.x);
        float v1y = ev1.y + DTC * (accE[j][3] - ev1.y);
        *(float2*)(out + i0)          = make_float2(fmaxf(v0x, 0.f), fmaxf(v0y, 0.f));
        *(float2*)(out + i1)          = make_float2(fmaxf(v1x, 0.f), fmaxf(v1y, 0.f));
        *(float2*)(out + OFF_VE + i0) = make_float2(v0x, v0y);
        *(float2*)(out + OFF_VE + i1) = make_float2(v1x, v1y);
    }
    if (wn == 0) {
#pragma unroll
        for (int j = 0; j < 3; j++) {
            const int col = j * 8 + 2 * lc;
            if (col < NI_) {
                const size_t i0 = ((size_t)r0 * C_ + c) * NI_ + col;
                const size_t i1 = ((size_t)r1 * C_ + c) * NI_ + col;
                float2 iv0 = *(const float2*)(i_v + i0);
                float2 iv1 = *(const float2*)(i_v + i1);
                float v0x = iv0.x + DTC * (accI[j][0] - iv0.x);
                float v0y = iv0.y + DTC * (accI[j][1] - iv0.y);
                float v1x = iv1.x + DTC * (accI[j][2] - iv1.x);
                float v1y = iv1.y + DTC * (accI[j][3] - iv1.y);
                *(float2*)(out + OFF_RI + i0) = make_float2(fmaxf(v0x, 0.f), fmaxf(v0y, 0.f));
                *(float2*)(out + OFF_RI + i1) = make_float2(fmaxf(v1x, 0.f), fmaxf(v1y, 0.f));
                *(float2*)(out + OFF_VI + i0) = make_float2(v0x, v0y);
                *(float2*)(out + OFF_VI + i1) = make_float2(v1x, v1y);
            }
        }
    }
}

extern "C" void kernel_launch(void* const* d_in, const int* in_sizes, int n_in,
                              void* d_out, int out_size) {
    (void)in_sizes; (void)n_in; (void)out_size;
    cudaFuncSetAttribute(ei_bf16, cudaFuncAttributeMaxDynamicSharedMemorySize,
                         SMEM_BYTES);
    ei_bf16<<<C_, 256, SMEM_BYTES>>>(
        (const float*)d_in[0],   // thal
        (const float*)d_in[1],   // thal_increments
        (const float*)d_in[2],   // l23_fb
        (const float*)d_in[3],   // r_e
        (const float*)d_in[4],   // r_i
        (const float*)d_in[5],   // e_v
        (const float*)d_in[6],   // i_v
        (const float*)d_in[7],   // input_proj
        (const float*)d_in[8],   // feedback_proj
        (const float*)d_in[9],   // W_ee
        (const float*)d_in[10],  // W_ei
        (const float*)d_in[11],  // W_ie
        (float*)d_out);
}

// round 5
// speedup vs baseline: 1.9708x; 1.1173x over previous
#include <cuda_runtime.h>
#include <cstdint>

constexpr int B_ = 64, C_ = 512, NE_ = 80, NI_ = 20, E_ = 512;
#define DTC 0.1f

// stage tile: A [64 x 32] + W [80 x 32], row stride 40 floats (conflict-free
// for half-warp phased LDS.64 fragment reads and cp.async 16B stores).
constexpr int LDSW   = 40;
constexpr int A_F    = 64 * LDSW;          // 2560 floats
constexpr int W_F    = 80 * LDSW;          // 3200 floats
constexpr int STAGE_F = A_F + W_F;         // 5760 floats = 23040 B
constexpr int NSTAGE  = 3;
// persistent W_ei buffer: 24 rows x 88 stride (rows 20-23 zeroed), K=80 cols
constexpr int LDWEI  = 88;
constexpr int WEI_OFF = NSTAGE * STAGE_F;          // 17280 floats
constexpr int WEI_F   = 24 * LDWEI;                // 2112 floats
constexpr int SMEM_BYTES = (WEI_OFF + WEI_F) * 4;  // 77568 B

constexpr size_t OFF_RI = (size_t)B_ * C_ * NE_;
constexpr size_t OFF_VE = OFF_RI + (size_t)B_ * C_ * NI_;
constexpr size_t OFF_VI = OFF_VE + (size_t)B_ * C_ * NE_;

// ---------------- helpers ----------------
__device__ __forceinline__ uint32_t s2u(const void* p) {
    uint32_t a;
    asm("{ .reg .u64 t; cvta.to.shared.u64 t, %1; cvt.u32.u64 %0, t; }" : "=r"(a) : "l"(p));
    return a;
}
__device__ __forceinline__ void cpa16(uint32_t dst, const float* src) {
    asm volatile("cp.async.cg.shared.global [%0], [%1], 16;" :: "r"(dst), "l"(src));
}
__device__ __forceinline__ void cpa16z(uint32_t dst, const float* src) {
    asm volatile("cp.async.cg.shared.global [%0], [%1], 16, 0;" :: "r"(dst), "l"(src));
}
#define CP_COMMIT() asm volatile("cp.async.commit_group;" ::: "memory")
#define CP_WAIT1()  asm volatile("cp.async.wait_group 1;" ::: "memory")
#define CP_WAIT0()  asm volatile("cp.async.wait_group 0;" ::: "memory")

__device__ __forceinline__ uint32_t bfx2(float2 f) {
    uint32_t r;
    asm("cvt.rn.bf16x2.f32 %0, %1, %2;" : "=r"(r) : "f"(f.y), "f"(f.x));
    return r;
}
__device__ __forceinline__ void mma16(float d[4], uint32_t a0, uint32_t a1,
                                      uint32_t a2, uint32_t a3,
                                      uint32_t b0, uint32_t b1) {
    asm("mma.sync.aligned.m16n8k16.row.col.f32.bf16.bf16.f32 "
        "{%0,%1,%2,%3}, {%4,%5,%6,%7}, {%8,%9}, {%0,%1,%2,%3};"
        : "+f"(d[0]), "+f"(d[1]), "+f"(d[2]), "+f"(d[3])
        : "r"(a0), "r"(a1), "r"(a2), "r"(a3), "r"(b0), "r"(b1));
}

// ---------------- chunk table ----------------
// ci 0-15 : I_ext  k0=ci*32           (A=thal_inc, W=input_proj), ksteps=2
// ci 16-18: I_fb   k0=(ci-16)*32      (A=l23_fb, W=feedback_proj), ksteps 2,2,1
// ci 19-21: I_ee   k0=(ci-19)*32      (A=r_e, W=W_ee), ksteps 2,2,1; +I_ei via Wei
// ci 22   : I_ie   K=20 pad 32        (A=r_i, W=W_ie, negated A), ksteps=2
__device__ __forceinline__ void prefetch(
    int ci, int c, int t, float* sm,
    const float* thal_inc, const float* l23_fb, const float* r_e,
    const float* r_i, const float* input_proj, const float* feedback_proj,
    const float* W_ee, const float* W_ei, const float* W_ie) {
    const int slot = ci % NSTAGE;
    const uint32_t asb = s2u(sm + slot * STAGE_F);
    const uint32_t wsb = asb + A_F * 4;

    if (ci < 16) {
        const int k0 = ci * 32;
        for (int idx = t; idx < 1152; idx += 256) {
            if (idx < 512) {
                int row = idx >> 3, g = idx & 7;
                cpa16(asb + (row * LDSW + g * 4) * 4,
                      thal_inc + ((size_t)row * C_ + c) * E_ + k0 + g * 4);
            } else {
                int j = idx - 512, row = j >> 3, g = j & 7;
                cpa16(wsb + (row * LDSW + g * 4) * 4,
                      input_proj + ((size_t)c * NE_ + row) * E_ + k0 + g * 4);
            }
        }
    } else if (ci == 16 || ci == 17 || ci == 19 || ci == 20) {
        const bool isB = ci < 19;
        const int k0 = (ci - (isB ? 16 : 19)) * 32;
        const float* Ap = isB ? l23_fb : r_e;
        const float* Wp = isB ? feedback_proj : W_ee;
        const int tot = (ci == 19) ? 1152 + 480 : 1152;
        const uint32_t weib = s2u(sm + WEI_OFF);
        for (int idx = t; idx < tot; idx += 256) {
            if (idx < 512) {
                int row = idx >> 3, g = idx & 7;
                cpa16(asb + (row * LDSW + g * 4) * 4,
                      Ap + ((size_t)row * C_ + c) * NE_ + k0 + g * 4);
            } else if (idx < 1152) {
                int j = idx - 512, row = j >> 3, g = j & 7;
                cpa16(wsb + (row * LDSW + g * 4) * 4,
                      Wp + ((size_t)c * NE_ + row) * NE_ + k0 + g * 4);
            } else {
                int j = idx - 1152, row = j / 20, g = j % 20;
                uint32_t dst = weib + (row * LDWEI + g * 4) * 4;
                const float* src = W_ei + ((size_t)c * NI_ + (row < NI_ ? row : 0)) * NE_ + g * 4;
                if (row < NI_) cpa16(dst, src); else cpa16z(dst, src);
            }
        }
    } else if (ci == 18 || ci == 21) {
        const bool isB = ci == 18;
        const float* Ap = isB ? l23_fb : r_e;
        const float* Wp = isB ? feedback_proj : W_ee;
        for (int idx = t; idx < 576; idx += 256) {
            if (idx < 256) {
                int row = idx >> 2, g = idx & 3;
                cpa16(asb + (row * LDSW + g * 4) * 4,
                      Ap + ((size_t)row * C_ + c) * NE_ + 64 + g * 4);
            } else {
                int j = idx - 256, row = j >> 2, g = j & 3;
                cpa16(wsb + (row * LDSW + g * 4) * 4,
                      Wp + ((size_t)c * NE_ + row) * NE_ + 64 + g * 4);
            }
        }
    } else {  // ci == 22
        for (int idx = t; idx < 1152; idx += 256) {
            if (idx < 512) {
                int row = idx >> 3, g = idx & 7;
                uint32_t dst = asb + (row * LDSW + g * 4) * 4;
                const float* src = r_i + ((size_t)row * C_ + c) * NI_;
                if (g < 5) cpa16(dst, src + g * 4); else cpa16z(dst, src);
            } else {
                int j = idx - 512, row = j >> 3, g = j & 7;
                uint32_t dst = wsb + (row * LDSW + g * 4) * 4;
                const float* src = W_ie + ((size_t)c * NE_ + row) * NI_;
                if (g < 5) cpa16(dst, src + g * 4); else cpa16z(dst, src);
            }
        }
    }
}

__global__ void __launch_bounds__(256, 3)
ei_bf16(const float* __restrict__ thal, const float* __restrict__ thal_inc,
        const float* __restrict__ l23_fb, const float* __restrict__ r_e,
        const float* __restrict__ r_i, const float* __restrict__ e_v,
        const float* __restrict__ i_v, const float* __restrict__ input_proj,
        const float* __restrict__ feedback_proj, const float* __restrict__ W_ee,
        const float* __restrict__ W_ei, const float* __restrict__ W_ie,
        float* __restrict__ out) {
    extern __shared__ float sm[];
    const int t = threadIdx.x, c = blockIdx.x;
    const int w = t >> 5, lane = t & 31;
    const int wm = w >> 1, wn = w & 1;
    const int m0 = wm * 16, lm = lane >> 2, lc = lane & 3;

    float accE[5][4], accI[3][4];
#pragma unroll
    for (int j = 0; j < 5; j++)
#pragma unroll
        for (int q = 0; q < 4; q++) accE[j][q] = 0.f;
#pragma unroll
    for (int j = 0; j < 3; j++)
#pragma unroll
        for (int q = 0; q < 4; q++) accI[j][q] = 0.f;

    prefetch(0, c, t, sm, thal_inc, l23_fb, r_e, r_i,
             input_proj, feedback_proj, W_ee, W_ei, W_ie);
    CP_COMMIT();
    prefetch(1, c, t, sm, thal_inc, l23_fb, r_e, r_i,
             input_proj, feedback_proj, W_ee, W_ei, W_ie);
    CP_COMMIT();

    const float* Wei = sm + WEI_OFF;

    for (int ci = 0; ci < 23; ci++) {
        if (ci == 22) CP_WAIT0(); else CP_WAIT1();
        __syncthreads();   // chunk ci visible to all; chunk ci-1 readers done
        if (ci + 2 <= 22) {
            prefetch(ci + 2, c, t, sm, thal_inc, l23_fb, r_e, r_i,
                     input_proj, feedback_proj, W_ee, W_ei, W_ie);
            CP_COMMIT();
        }

        const float* As = sm + (ci % NSTAGE) * STAGE_F;
        const float* Ws = As + A_F;
        const int ksteps = (ci == 18 || ci == 21) ? 1 : 2;
        const bool doI = (ci >= 19 && ci <= 21);
        const bool neg = (ci == 22);
        const int kei0 = (ci - 19) * 32;

#pragma unroll 2
        for (int ks = 0; ks < ksteps; ks++) {
            const int kb = ks * 16;
            const float* ap = As + (m0 + lm) * LDSW + kb + 2 * lc;
            float2 fa0 = *(const float2*)(ap);
            float2 fa1 = *(const float2*)(ap + 8 * LDSW);
            float2 fa2 = *(const float2*)(ap + 8);
            float2 fa3 = *(const float2*)(ap + 8 * LDSW + 8);
            if (ci < 16) {   // fold broadcast thal (L2-hot) into fragments
                const float* tp = thal + (size_t)(m0 + lm) * E_ + ci * 32 + kb + 2 * lc;
                float2 t00 = __ldg((const float2*)(tp));
                float2 t01 = __ldg((const float2*)(tp + 8));
                float2 t10 = __ldg((const float2*)(tp + 8 * E_));
                float2 t11 = __ldg((const float2*)(tp + 8 * E_ + 8));
                fa0.x += t00.x; fa0.y += t00.y; fa2.x += t01.x; fa2.y += t01.y;
                fa1.x += t10.x; fa1.y += t10.y; fa3.x += t11.x; fa3.y += t11.y;
            }
            if (neg) {
                fa0.x = -fa0.x; fa0.y = -fa0.y; fa1.x = -fa1.x; fa1.y = -fa1.y;
                fa2.x = -fa2.x; fa2.y = -fa2.y; fa3.x = -fa3.x; fa3.y = -fa3.y;
            }
            const uint32_t a0 = bfx2(fa0), a1 = bfx2(fa1), a2 = bfx2(fa2), a3 = bfx2(fa3);
#pragma unroll
            for (int j = 0; j < 5; j++) {
                const float* wp = Ws + (wn * 40 + j * 8 + lm) * LDSW + kb + 2 * lc;
                uint32_t b0 = bfx2(*(const float2*)(wp));
                uint32_t b1 = bfx2(*(const float2*)(wp + 8));
                mma16(accE[j], a0, a1, a2, a3, b0, b1);
            }
            if (doI && wn == 0) {
#pragma unroll
                for (int j = 0; j < 3; j++) {
                    const float* wp = Wei + (j * 8 + lm) * LDWEI + kei0 + kb + 2 * lc;
                    uint32_t b0 = bfx2(*(const float2*)(wp));
                    uint32_t b1 = bfx2(*(const float2*)(wp + 8));
                    mma16(accI[j], a0, a1, a2, a3, b0, b1);
                }
            }
        }
    }

    // ---------------- epilogue: leaky integration + relu ----------------
    const int r0 = m0 + lm, r1 = r0 + 8;
#pragma unroll
    for (int j = 0; j < 5; j++) {
        const int col = wn * 40 + j * 8 + 2 * lc;
        const size_t i0 = ((size_t)r0 * C_ + c) * NE_ + col;
        const size_t i1 = ((size_t)r1 * C_ + c) * NE_ + col;
        float2 ev0 = *(const float2*)(e_v + i0);
        float2 ev1 = *(const float2*)(e_v + i1);
        float v0x = ev0.x + DTC * (accE[j][0] - ev0.x);
        float v0y = ev0.y + DTC * (accE[j][1] - ev0.y);
        float v1x = ev1.x + DTC * (accE[j][2] - ev1.x);
        float v1y = ev1.y + DTC * (accE[j][3] - ev1.y);
        *(float2*)(out + i0)          = make_float2(fmaxf(v0x, 0.f), fmaxf(v0y, 0.f));
        *(float2*)(out + i1)          = make_float2(fmaxf(v1x, 0.f), fmaxf(v1y, 0.f));
        *(float2*)(out + OFF_VE + i0) = make_float2(v0x, v0y);
        *(float2*)(out + OFF_VE + i1) = make_float2(v1x, v1y);
    }
    if (wn == 0) {
#pragma unroll
        for (int j = 0; j < 3; j++) {
            const int col = j * 8 + 2 * lc;
            if (col < NI_) {
                const size_t i0 = ((size_t)r0 * C_ + c) * NI_ + col;
                const size_t i1 = ((size_t)r1 * C_ + c) * NI_ + col;
                float2 iv0 = *(const float2*)(i_v + i0);
                float2 iv1 = *(const float2*)(i_v + i1);
                float v0x = iv0.x + DTC * (accI[j][0] - iv0.x);
                float v0y = iv0.y + DTC * (accI[j][1] - iv0.y);
                float v1x = iv1.x + DTC * (accI[j][2] - iv1.x);
                float v1y = iv1.y + DTC * (accI[j][3] - iv1.y);
                *(float2*)(out + OFF_RI + i0) = make_float2(fmaxf(v0x, 0.f), fmaxf(v0y, 0.f));
                *(float2*)(out + OFF_RI + i1) = make_float2(fmaxf(v1x, 0.f), fmaxf(v1y, 0.f));
                *(float2*)(out + OFF_VI + i0) = make_float2(v0x, v0y);
                *(float2*)(out + OFF_VI + i1) = make_float2(v1x, v1y);
            }
        }
    }
}

extern "C" void kernel_launch(void* const* d_in, const int* in_sizes, int n_in,
                              void* d_out, int out_size) {
    (void)in_sizes; (void)n_in; (void)out_size;
    cudaFuncSetAttribute(ei_bf16, cudaFuncAttributeMaxDynamicSharedMemorySize,
                         SMEM_BYTES);
    ei_bf16<<<C_, 256, SMEM_BYTES>>>(
        (const float*)d_in[0],   // thal
        (const float*)d_in[1],   // thal_increments
        (const float*)d_in[2],   // l23_fb
        (const float*)d_in[3],   // r_e
        (const float*)d_in[4],   // r_i
        (const float*)d_in[5],   // e_v
        (const float*)d_in[6],   // i_v
        (const float*)d_in[7],   // input_proj
        (const float*)d_in[8],   // feedback_proj
        (const float*)d_in[9],   // W_ee
        (const float*)d_in[10],  // W_ei
        (const float*)d_in[11],  // W_ie
        (float*)d_out);
}